// round 5
// baseline (speedup 1.0000x reference)
#include <cuda_runtime.h>
#include <cstdint>

// Problem constants
#define NROWS 10000
#define NFEAT 3000
#define NHID  32
#define KCLUST 10
#define ALPHAF 0.2f

// Tiling: 125 CTAs x 80 rows = 10000 exact. 4 warps; warp w -> mtile w, warp 0 also mtile 4.
#define MT 80
#define KC 32
#define NSTAGE 8
#define THREADS 128

#define A_STRIDE 36                                   // floats; bank = (4g+tig) -> conflict-free
#define STAGE_FLOATS ((MT + NHID) * A_STRIDE)         // 4032
#define STAGE_BYTES  (STAGE_FLOATS * 4)               // 16128
#define SMEM_TOTAL   (NSTAGE * STAGE_BYTES)           // 129024

// Scratch (device globals; B operands stored pre-rounded to tf32)
__device__ __align__(16) float g_WT[NHID * NFEAT];        // W^T   [32, 3000]
__device__ __align__(16) float g_supportT[NHID * NROWS];  // (xW)^T [32, 10000]

// ---------------------------------------------------------------------------
// Helpers
// ---------------------------------------------------------------------------
__device__ __forceinline__ uint32_t smem_u32(const void* p) {
    return (uint32_t)__cvta_generic_to_shared(p);
}
__device__ __forceinline__ void cp_async16(uint32_t saddr, const void* gaddr, int src_bytes) {
    asm volatile("cp.async.cg.shared.global [%0], [%1], 16, %2;"
                 :: "r"(saddr), "l"(gaddr), "r"(src_bytes));
}
__device__ __forceinline__ uint32_t cvt_tf32(float x) {   // round-to-nearest tf32 (unbiased)
    uint32_t r;
    asm("cvt.rna.tf32.f32 %0, %1;" : "=r"(r) : "f"(x));
    return r;
}
__device__ __forceinline__ void mma_tf32(float* c, const uint32_t* a, const uint32_t* b) {
    asm volatile("mma.sync.aligned.m16n8k8.row.col.f32.tf32.tf32.f32 "
                 "{%0,%1,%2,%3}, {%4,%5,%6,%7}, {%8,%9}, {%0,%1,%2,%3};"
                 : "+f"(c[0]), "+f"(c[1]), "+f"(c[2]), "+f"(c[3])
                 : "r"(a[0]), "r"(a[1]), "r"(a[2]), "r"(a[3]),
                   "r"(b[0]), "r"(b[1]));
}

// ---------------------------------------------------------------------------
// W[3000,32] -> WT[32,3000], pre-rounded to tf32
// ---------------------------------------------------------------------------
__global__ void transposeW_kernel(const float* __restrict__ W)
{
    int idx = blockIdx.x * blockDim.x + threadIdx.x;
    if (idx < NHID * NFEAT) {
        int n = idx / NFEAT;
        int k = idx - n * NFEAT;
        g_WT[idx] = __uint_as_float(cvt_tf32(W[(size_t)k * NHID + n]));
    }
}

// ---------------------------------------------------------------------------
// Fused tf32 mma.sync GEMM:  D[10000,32] = A[10000,Kd] @ BT[32,Kd]^T
//   mode 0: B = g_WT       -> epilogue writes g_supportT (tf32-rounded)
//   mode 1: B = g_supportT -> epilogue: z = D + bias -> out_z; student-t q -> out_q
// ---------------------------------------------------------------------------
__global__ void __launch_bounds__(THREADS)
gcn_mma_kernel(const float* __restrict__ A, int Kd, int mode,
               const float* __restrict__ bias, const float* __restrict__ mu,
               float* __restrict__ out_z, float* __restrict__ out_q)
{
    extern __shared__ float smem[];
    const uint32_t sbase = smem_u32(smem);
    const int tid  = threadIdx.x;
    const int row0 = blockIdx.x * MT;
    const int nchunks = (Kd + KC - 1) / KC;

    const float* __restrict__ BT = (mode == 0) ? g_WT : g_supportT;

    const int wid  = tid >> 5;
    const int lane = tid & 31;
    const int g    = lane >> 2;   // 0..7
    const int tig  = lane & 3;    // 0..3
    const int nmt  = (wid == 0) ? 2 : 1;   // warp 0 owns mtiles {0,4}; warp w owns {w}

    float acc[2][4][4];
#pragma unroll
    for (int i = 0; i < 2; i++)
#pragma unroll
        for (int nt = 0; nt < 4; nt++)
#pragma unroll
            for (int r = 0; r < 4; r++) acc[i][nt][r] = 0.0f;

    // ---- stage one K-chunk (A: 80x32 fp32, B: 32x32 fp32) into ring slot ----
    auto load_chunk = [&](int c) {
        const int s  = c & (NSTAGE - 1);
        const int k0 = c * KC;
        const uint32_t a_s = sbase + s * STAGE_BYTES;
        const uint32_t b_s = a_s + MT * A_STRIDE * 4;
        // A: 640 float4 -> 5 per thread (rows always in range: exact tiling)
#pragma unroll
        for (int t = 0; t < 5; t++) {
            int idx = tid + t * THREADS;
            int r   = idx >> 3;
            int c4  = idx & 7;
            int gk  = k0 + c4 * 4;
            int remk = Kd - gk;
            int bytes = remk >= 4 ? 16 : (remk > 0 ? remk * 4 : 0);
            const float* src = bytes ? (A + (size_t)(row0 + r) * Kd + gk) : A;
            cp_async16(a_s + (uint32_t)(r * A_STRIDE + c4 * 4) * 4, src, bytes);
        }
        // B: 256 float4 -> 2 per thread
#pragma unroll
        for (int t = 0; t < 2; t++) {
            int idx = tid + t * THREADS;
            int r   = idx >> 3;
            int c4  = idx & 7;
            int gk  = k0 + c4 * 4;
            int remk = Kd - gk;
            int bytes = remk >= 4 ? 16 : (remk > 0 ? remk * 4 : 0);
            const float* src = bytes ? (BT + (size_t)r * Kd + gk) : BT;
            cp_async16(b_s + (uint32_t)(r * A_STRIDE + c4 * 4) * 4, src, bytes);
        }
        asm volatile("cp.async.commit_group;" ::: "memory");
    };

    // prologue: NSTAGE-1 stages in flight
    for (int c = 0; c < NSTAGE - 1; c++) load_chunk(c);

    // ---- mainloop: one wait + one barrier per chunk ----
    for (int c = 0; c < nchunks; c++) {
        asm volatile("cp.async.wait_group %0;" :: "n"(NSTAGE - 2));  // chunk c landed
        __syncthreads();   // also guarantees all warps finished chunk c-1 (slot reused below)
        if (c + NSTAGE - 1 < nchunks) load_chunk(c + NSTAGE - 1);
        else asm volatile("cp.async.commit_group;" ::: "memory");    // keep group count in lockstep

        const float* As = smem + (size_t)(c & (NSTAGE - 1)) * STAGE_FLOATS;
        const float* Bs = As + MT * A_STRIDE;

#pragma unroll
        for (int kt = 0; kt < 4; kt++) {
            uint32_t b[4][2];
#pragma unroll
            for (int nt = 0; nt < 4; nt++) {   // B pre-rounded: no cvt needed
                b[nt][0] = __float_as_uint(Bs[(nt * 8 + g) * A_STRIDE + kt * 8 + tig]);
                b[nt][1] = __float_as_uint(Bs[(nt * 8 + g) * A_STRIDE + kt * 8 + tig + 4]);
            }
#pragma unroll
            for (int i = 0; i < 2; i++) {
                if (i < nmt) {
                    const int rb = (i ? 4 : wid) * 16;
                    uint32_t a[4];
                    a[0] = cvt_tf32(As[(rb + g)     * A_STRIDE + kt * 8 + tig]);
                    a[1] = cvt_tf32(As[(rb + g + 8) * A_STRIDE + kt * 8 + tig]);
                    a[2] = cvt_tf32(As[(rb + g)     * A_STRIDE + kt * 8 + tig + 4]);
                    a[3] = cvt_tf32(As[(rb + g + 8) * A_STRIDE + kt * 8 + tig + 4]);
#pragma unroll
                    for (int nt = 0; nt < 4; nt++)
                        mma_tf32(acc[i][nt], a, b[nt]);
                }
            }
        }
    }
    __syncthreads();

    // ---- epilogue ----
    if (mode == 0) {
        // supportT[n][m] = tf32_round(D[m][n])
#pragma unroll
        for (int i = 0; i < 2; i++) if (i < nmt) {
            const int mt = i ? 4 : wid;
#pragma unroll
            for (int nt = 0; nt < 4; nt++)
#pragma unroll
                for (int r = 0; r < 4; r++) {
                    int m = row0 + mt * 16 + g + ((r & 2) ? 8 : 0);
                    int n = nt * 8 + tig * 2 + (r & 1);
                    g_supportT[(size_t)n * NROWS + m] =
                        __uint_as_float(cvt_tf32(acc[i][nt][r]));
                }
        }
    } else {
        // stage z (+bias) rows in smem, then thread-per-row z/q
        float* zs = smem;   // [MT][A_STRIDE], reuses stage 0
#pragma unroll
        for (int i = 0; i < 2; i++) if (i < nmt) {
            const int mt = i ? 4 : wid;
#pragma unroll
            for (int nt = 0; nt < 4; nt++)
#pragma unroll
                for (int r = 0; r < 4; r++) {
                    int rr = mt * 16 + g + ((r & 2) ? 8 : 0);
                    int n  = nt * 8 + tig * 2 + (r & 1);
                    zs[rr * A_STRIDE + n] = acc[i][nt][r] + __ldg(bias + n);
                }
        }
        __syncthreads();
        if (tid < MT) {
            const int m = row0 + tid;
            float z[NHID];
#pragma unroll
            for (int k = 0; k < NHID; k += 4) {
                float4 v = *reinterpret_cast<const float4*>(zs + tid * A_STRIDE + k);
                z[k] = v.x; z[k + 1] = v.y; z[k + 2] = v.z; z[k + 3] = v.w;
                *reinterpret_cast<float4*>(out_z + (size_t)m * NHID + k) = v;
            }
            float q[KCLUST];
            float qsum = 0.0f;
#pragma unroll
            for (int j = 0; j < KCLUST; j++) {
                float d2 = 0.0f;
#pragma unroll
                for (int k = 0; k < NHID; k++) {
                    float d = z[k] - __ldg(mu + j * NHID + k);
                    d2 = fmaf(d, d, d2);
                }
                float t  = 1.0f / (1.0f + d2 * (1.0f / ALPHAF) + 1e-8f);
                float qj = __powf(t, ALPHAF + 1.0f) * 0.5f;
                q[j] = qj;
                qsum += qj;
            }
            float inv = 1.0f / qsum;
#pragma unroll
            for (int j = 0; j < KCLUST; j++)
                out_q[(size_t)m * KCLUST + j] = q[j] * inv;
        }
    }
}

// ---------------------------------------------------------------------------
// Launch: transpose W -> GEMM1 (x@W -> supportT) -> GEMM2 fused (z, q)
// ---------------------------------------------------------------------------
extern "C" void kernel_launch(void* const* d_in, const int* in_sizes, int n_in,
                              void* d_out, int out_size)
{
    const float* x   = (const float*)d_in[0];   // [10000, 3000]
    const float* adj = (const float*)d_in[1];   // [10000, 10000]
    const float* W   = (const float*)d_in[2];   // [3000, 32]
    const float* b   = (const float*)d_in[3];   // [32]
    const float* mu  = (const float*)d_in[4];   // [10, 32]

    float* out   = (float*)d_out;
    float* out_z = out;                          // [10000, 32]
    float* out_q = out + (size_t)NROWS * NHID;   // [10000, 10]

    cudaFuncSetAttribute(gcn_mma_kernel,
                         cudaFuncAttributeMaxDynamicSharedMemorySize, SMEM_TOTAL);

    const int grid = NROWS / MT;   // 125, exact

    transposeW_kernel<<<(NHID * NFEAT + 255) / 256, 256>>>(W);
    gcn_mma_kernel<<<grid, THREADS, SMEM_TOTAL>>>(
        x, NFEAT, 0, nullptr, nullptr, nullptr, nullptr);
    gcn_mma_kernel<<<grid, THREADS, SMEM_TOTAL>>>(
        adj, NROWS, 1, b, mu, out_z, out_q);
}

// round 6
// speedup vs baseline: 1.4076x; 1.4076x over previous
#include <cuda_runtime.h>
#include <cstdint>

// Problem constants
#define NROWS 10000
#define NFEAT 3000
#define NHID  32
#define KCLUST 10
#define ALPHAF 0.2f

// Tiling: 125 CTAs x 80 rows = 10000 exact. 8 warps; warps 0-4 own mtiles 0-4.
#define MT 80
#define KC 32
#define NSTAGE 8
#define THREADS 256

#define A_STRIDE 36                                   // floats; bank = (4g+tig) -> conflict-free
#define STAGE_FLOATS ((MT + NHID) * A_STRIDE)         // 4032
#define STAGE_BYTES  (STAGE_FLOATS * 4)               // 16128
#define SMEM_TOTAL   (NSTAGE * STAGE_BYTES)           // 129024

// Scratch (device globals; B operands stored pre-rounded to tf32)
__device__ __align__(16) float g_WT[NHID * NFEAT];        // W^T   [32, 3000]
__device__ __align__(16) float g_supportT[NHID * NROWS];  // (xW)^T [32, 10000]

// ---------------------------------------------------------------------------
// Helpers
// ---------------------------------------------------------------------------
__device__ __forceinline__ void cp_async16(uint32_t saddr, const void* gaddr, int src_bytes) {
    asm volatile("cp.async.cg.shared.global [%0], [%1], 16, %2;"
                 :: "r"(saddr), "l"(gaddr), "r"(src_bytes));
}
__device__ __forceinline__ uint32_t smem_u32(const void* p) {
    return (uint32_t)__cvta_generic_to_shared(p);
}
__device__ __forceinline__ uint32_t cvt_tf32(float x) {   // round-to-nearest tf32 (unbiased)
    uint32_t r;
    asm("cvt.rna.tf32.f32 %0, %1;" : "=r"(r) : "f"(x));
    return r;
}
__device__ __forceinline__ void mma_tf32(float* c, const uint32_t* a, const uint32_t* b) {
    asm volatile("mma.sync.aligned.m16n8k8.row.col.f32.tf32.tf32.f32 "
                 "{%0,%1,%2,%3}, {%4,%5,%6,%7}, {%8,%9}, {%0,%1,%2,%3};"
                 : "+f"(c[0]), "+f"(c[1]), "+f"(c[2]), "+f"(c[3])
                 : "r"(a[0]), "r"(a[1]), "r"(a[2]), "r"(a[3]),
                   "r"(b[0]), "r"(b[1]));
}

// ---------------------------------------------------------------------------
// W[3000,32] -> WT[32,3000], pre-rounded to tf32
// ---------------------------------------------------------------------------
__global__ void transposeW_kernel(const float* __restrict__ W)
{
    int idx = blockIdx.x * blockDim.x + threadIdx.x;
    if (idx < NHID * NFEAT) {
        int n = idx / NFEAT;
        int k = idx - n * NFEAT;
        g_WT[idx] = __uint_as_float(cvt_tf32(W[(size_t)k * NHID + n]));
    }
}

// ---------------------------------------------------------------------------
// Fused tf32 mma.sync GEMM:  D[10000,32] = A[10000,Kd] @ BT[32,Kd]^T
//   mode 0: B = g_WT       -> epilogue writes g_supportT (tf32-rounded)
//   mode 1: B = g_supportT -> epilogue: z = D + bias -> out_z; student-t q -> out_q
// 256 threads: warps 0-4 compute one mtile each; all warps load.
// ---------------------------------------------------------------------------
__global__ void __launch_bounds__(THREADS)
gcn_mma_kernel(const float* __restrict__ A, int Kd, int mode,
               const float* __restrict__ bias, const float* __restrict__ mu,
               float* __restrict__ out_z, float* __restrict__ out_q)
{
    extern __shared__ float smem[];
    const uint32_t sbase = smem_u32(smem);
    const int tid  = threadIdx.x;
    const int row0 = blockIdx.x * MT;
    const int nchunks = (Kd + KC - 1) / KC;

    const float* __restrict__ BT = (mode == 0) ? g_WT : g_supportT;

    const int wid  = tid >> 5;
    const int lane = tid & 31;
    const int g    = lane >> 2;   // 0..7
    const int tig  = lane & 3;    // 0..3
    const bool mma_warp = (wid < 5);
    const int rb   = wid * 16;    // mtile row base (valid for wid<5)

    float acc[4][4];
#pragma unroll
    for (int nt = 0; nt < 4; nt++)
#pragma unroll
        for (int r = 0; r < 4; r++) acc[nt][r] = 0.0f;

    // ---- stage one K-chunk (A: 80x32 fp32, B: 32x32 fp32) into ring slot ----
    auto load_chunk = [&](int c) {
        const int s  = c & (NSTAGE - 1);
        const int k0 = c * KC;
        const uint32_t a_s = sbase + s * STAGE_BYTES;
        const uint32_t b_s = a_s + MT * A_STRIDE * 4;
        // A: 640 float4 over 256 threads -> up to 3 per thread
#pragma unroll
        for (int t = 0; t < 3; t++) {
            int idx = tid + t * THREADS;
            if (idx < (MT * KC / 4)) {
                int r   = idx >> 3;
                int c4  = idx & 7;
                int gk  = k0 + c4 * 4;
                int remk = Kd - gk;
                int bytes = remk >= 4 ? 16 : (remk > 0 ? remk * 4 : 0);
                const float* src = bytes ? (A + (size_t)(row0 + r) * Kd + gk) : A;
                cp_async16(a_s + (uint32_t)(r * A_STRIDE + c4 * 4) * 4, src, bytes);
            }
        }
        // B: 256 float4 -> 1 per thread
        {
            int r   = tid >> 3;
            int c4  = tid & 7;
            int gk  = k0 + c4 * 4;
            int remk = Kd - gk;
            int bytes = remk >= 4 ? 16 : (remk > 0 ? remk * 4 : 0);
            const float* src = bytes ? (BT + (size_t)r * Kd + gk) : BT;
            cp_async16(b_s + (uint32_t)(r * A_STRIDE + c4 * 4) * 4, src, bytes);
        }
        asm volatile("cp.async.commit_group;" ::: "memory");
    };

    // prologue: NSTAGE-1 stages in flight
    for (int c = 0; c < NSTAGE - 1; c++) load_chunk(c);

    // ---- mainloop: one wait + one barrier per chunk ----
    for (int c = 0; c < nchunks; c++) {
        asm volatile("cp.async.wait_group %0;" :: "n"(NSTAGE - 2));  // chunk c landed
        __syncthreads();   // all warps done with chunk c-1's slot; chunk c visible
        if (c + NSTAGE - 1 < nchunks) load_chunk(c + NSTAGE - 1);
        else asm volatile("cp.async.commit_group;" ::: "memory");    // keep group count in lockstep

        if (mma_warp) {
            const float* As = smem + (size_t)(c & (NSTAGE - 1)) * STAGE_FLOATS;
            const float* Bs = As + MT * A_STRIDE;
#pragma unroll
            for (int kt = 0; kt < 4; kt++) {
                uint32_t b[4][2];
#pragma unroll
                for (int nt = 0; nt < 4; nt++) {   // B pre-rounded: no cvt needed
                    b[nt][0] = __float_as_uint(Bs[(nt * 8 + g) * A_STRIDE + kt * 8 + tig]);
                    b[nt][1] = __float_as_uint(Bs[(nt * 8 + g) * A_STRIDE + kt * 8 + tig + 4]);
                }
                uint32_t a[4];
                a[0] = cvt_tf32(As[(rb + g)     * A_STRIDE + kt * 8 + tig]);
                a[1] = cvt_tf32(As[(rb + g + 8) * A_STRIDE + kt * 8 + tig]);
                a[2] = cvt_tf32(As[(rb + g)     * A_STRIDE + kt * 8 + tig + 4]);
                a[3] = cvt_tf32(As[(rb + g + 8) * A_STRIDE + kt * 8 + tig + 4]);
#pragma unroll
                for (int nt = 0; nt < 4; nt++)
                    mma_tf32(acc[nt], a, b[nt]);
            }
        }
    }
    __syncthreads();

    // ---- epilogue ----
    if (mode == 0) {
        if (mma_warp) {
            // supportT[n][m] = tf32_round(D[m][n])
#pragma unroll
            for (int nt = 0; nt < 4; nt++)
#pragma unroll
                for (int r = 0; r < 4; r++) {
                    int m = row0 + rb + g + ((r & 2) ? 8 : 0);
                    int n = nt * 8 + tig * 2 + (r & 1);
                    g_supportT[(size_t)n * NROWS + m] =
                        __uint_as_float(cvt_tf32(acc[nt][r]));
                }
        }
    } else {
        // stage z (+bias) rows in smem, then thread-per-row z/q
        float* zs = smem;   // [MT][A_STRIDE], reuses stage 0
        if (mma_warp) {
#pragma unroll
            for (int nt = 0; nt < 4; nt++)
#pragma unroll
                for (int r = 0; r < 4; r++) {
                    int rr = rb + g + ((r & 2) ? 8 : 0);
                    int n  = nt * 8 + tig * 2 + (r & 1);
                    zs[rr * A_STRIDE + n] = acc[nt][r] + __ldg(bias + n);
                }
        }
        __syncthreads();
        if (tid < MT) {
            const int m = row0 + tid;
            float z[NHID];
#pragma unroll
            for (int k = 0; k < NHID; k += 4) {
                float4 v = *reinterpret_cast<const float4*>(zs + tid * A_STRIDE + k);
                z[k] = v.x; z[k + 1] = v.y; z[k + 2] = v.z; z[k + 3] = v.w;
                *reinterpret_cast<float4*>(out_z + (size_t)m * NHID + k) = v;
            }
            float q[KCLUST];
            float qsum = 0.0f;
#pragma unroll
            for (int j = 0; j < KCLUST; j++) {
                float d2 = 0.0f;
#pragma unroll
                for (int k = 0; k < NHID; k++) {
                    float d = z[k] - __ldg(mu + j * NHID + k);
                    d2 = fmaf(d, d, d2);
                }
                float t  = 1.0f / (1.0f + d2 * (1.0f / ALPHAF) + 1e-8f);
                float qj = __powf(t, ALPHAF + 1.0f) * 0.5f;
                q[j] = qj;
                qsum += qj;
            }
            float inv = 1.0f / qsum;
#pragma unroll
            for (int j = 0; j < KCLUST; j++)
                out_q[(size_t)m * KCLUST + j] = q[j] * inv;
        }
    }
}

// ---------------------------------------------------------------------------
// Launch: transpose W -> GEMM1 (x@W -> supportT) -> GEMM2 fused (z, q)
// ---------------------------------------------------------------------------
extern "C" void kernel_launch(void* const* d_in, const int* in_sizes, int n_in,
                              void* d_out, int out_size)
{
    const float* x   = (const float*)d_in[0];   // [10000, 3000]
    const float* adj = (const float*)d_in[1];   // [10000, 10000]
    const float* W   = (const float*)d_in[2];   // [3000, 32]
    const float* b   = (const float*)d_in[3];   // [32]
    const float* mu  = (const float*)d_in[4];   // [10, 32]

    float* out   = (float*)d_out;
    float* out_z = out;                          // [10000, 32]
    float* out_q = out + (size_t)NROWS * NHID;   // [10000, 10]

    cudaFuncSetAttribute(gcn_mma_kernel,
                         cudaFuncAttributeMaxDynamicSharedMemorySize, SMEM_TOTAL);

    const int grid = NROWS / MT;   // 125, exact

    transposeW_kernel<<<(NHID * NFEAT + 255) / 256, 256>>>(W);
    gcn_mma_kernel<<<grid, THREADS, SMEM_TOTAL>>>(
        x, NFEAT, 0, nullptr, nullptr, nullptr, nullptr);
    gcn_mma_kernel<<<grid, THREADS, SMEM_TOTAL>>>(
        adj, NROWS, 1, b, mu, out_z, out_q);
}

// round 10
// speedup vs baseline: 1.5049x; 1.0691x over previous
#include <cuda_runtime.h>
#include <cstdint>

// Problem constants
#define NROWS 10000
#define NFEAT 3000
#define NHID  32
#define KCLUST 10
#define ALPHAF 0.2f

// Tiling: 125 CTAs x 80 rows = 10000 exact.
// Warps 0-3: full mtiles 0-3 (16 rows each). Warps 4-7: mtile 4 split by kt.
#define MT 80
#define KC 32
#define NSTAGE 8
#define THREADS 256

#define A_STRIDE 36                         // floats; bank = 4g+tig -> conflict-free
#define A_FLOATS (MT * A_STRIDE)            // 2880
#define B_FLOATS (KC * NHID)                // 1024 (fragment-major block)
#define STAGE_FLOATS (A_FLOATS + B_FLOATS)  // 3904
#define STAGE_BYTES (STAGE_FLOATS * 4)      // 15616
#define SMEM_TOTAL (NSTAGE * STAGE_BYTES)   // 124928

#define CH1 ((NFEAT + KC - 1) / KC)         // 94  chunks for GEMM1
#define CH2 ((NROWS + KC - 1) / KC)         // 313 chunks for GEMM2

// Scratch: B operands in FRAGMENT-MAJOR layout, 1024 floats per K-chunk.
// Element (n, k): c=k/32, k'=k%32, kt=k'>>3, h=(k'>>2)&1, tig=k'&3,
//   pos = c*1024 + (kt*2+h)*128 + ((n&7)*4 + tig)*4 + (n>>3)
__device__ __align__(16) float g_WT[CH1 * B_FLOATS];        // W,  frag-major
__device__ __align__(16) float g_supportT[CH2 * B_FLOATS];  // xW, frag-major

// ---------------------------------------------------------------------------
// Helpers
// ---------------------------------------------------------------------------
__device__ __forceinline__ void cp_async16(uint32_t saddr, const void* gaddr, int src_bytes) {
    asm volatile("cp.async.cg.shared.global [%0], [%1], 16, %2;"
                 :: "r"(saddr), "l"(gaddr), "r"(src_bytes));
}
__device__ __forceinline__ uint32_t smem_u32(const void* p) {
    return (uint32_t)__cvta_generic_to_shared(p);
}
__device__ __forceinline__ uint32_t cvt_tf32(float x) {   // round-to-nearest tf32
    uint32_t r;
    asm("cvt.rna.tf32.f32 %0, %1;" : "=r"(r) : "f"(x));
    return r;
}
__device__ __forceinline__ void mma_tf32(float* c, const uint32_t* a, uint32_t b0, uint32_t b1) {
    asm volatile("mma.sync.aligned.m16n8k8.row.col.f32.tf32.tf32.f32 "
                 "{%0,%1,%2,%3}, {%4,%5,%6,%7}, {%8,%9}, {%0,%1,%2,%3};"
                 : "+f"(c[0]), "+f"(c[1]), "+f"(c[2]), "+f"(c[3])
                 : "r"(a[0]), "r"(a[1]), "r"(a[2]), "r"(a[3]), "r"(b0), "r"(b1));
}
// Store one value into a fragment-major B array (pre-rounded to tf32).
__device__ __forceinline__ void store_frag(float* dst, float v, int k, int n) {
    int c   = k >> 5;
    int kp  = k & 31;
    int vi  = ((kp >> 3) << 1) | ((kp >> 2) & 1);
    int ln  = ((n & 7) << 2) | (kp & 3);
    dst[c * B_FLOATS + vi * 128 + ln * 4 + (n >> 3)] = __uint_as_float(cvt_tf32(v));
}

// ---------------------------------------------------------------------------
// Producer: W[3000,32] -> g_WT (frag-major, zero-padded), + zero supportT pad
// ---------------------------------------------------------------------------
__global__ void transposeW_kernel(const float* __restrict__ W)
{
    int idx = blockIdx.x * blockDim.x + threadIdx.x;
    if (idx < CH1 * B_FLOATS) {
        int c   = idx >> 10;
        int rem = idx & 1023;
        int vi  = rem >> 7;
        int ln  = (rem >> 2) & 31;
        int nt  = rem & 3;
        int g   = ln >> 2, tig = ln & 3;
        int kt  = vi >> 1, h = vi & 1;
        int k   = c * KC + kt * 8 + 4 * h + tig;
        int n   = nt * 8 + g;
        g_WT[idx] = (k < NFEAT)
            ? __uint_as_float(cvt_tf32(W[(size_t)k * NHID + n])) : 0.0f;
    } else if (idx < CH1 * B_FLOATS + B_FLOATS) {
        // zero supportT's final (partial) chunk; GEMM1 overwrites the valid part
        g_supportT[(CH2 - 1) * B_FLOATS + (idx - CH1 * B_FLOATS)] = 0.0f;
    }
}

// ---------------------------------------------------------------------------
// One kt-step of the mma for a 16-row mtile at row base rb.
// ---------------------------------------------------------------------------
__device__ __forceinline__ void do_kt(const float* As, const float4* B4,
                                      int kt, int rb, int g, int tig,
                                      float acc[4][4])
{
    float4 blo = B4[(kt * 2 + 0) * 32 + (g * 4 + tig)];
    float4 bhi = B4[(kt * 2 + 1) * 32 + (g * 4 + tig)];
    uint32_t a[4];
    a[0] = cvt_tf32(As[(rb + g)     * A_STRIDE + kt * 8 + tig]);
    a[1] = cvt_tf32(As[(rb + g + 8) * A_STRIDE + kt * 8 + tig]);
    a[2] = cvt_tf32(As[(rb + g)     * A_STRIDE + kt * 8 + tig + 4]);
    a[3] = cvt_tf32(As[(rb + g + 8) * A_STRIDE + kt * 8 + tig + 4]);
    mma_tf32(acc[0], a, __float_as_uint(blo.x), __float_as_uint(bhi.x));
    mma_tf32(acc[1], a, __float_as_uint(blo.y), __float_as_uint(bhi.y));
    mma_tf32(acc[2], a, __float_as_uint(blo.z), __float_as_uint(bhi.z));
    mma_tf32(acc[3], a, __float_as_uint(blo.w), __float_as_uint(bhi.w));
}

// ---------------------------------------------------------------------------
// Fused tf32 mma GEMM:  D[10000,32] = A[10000,Kd] @ B  (B frag-major)
//   mode 0: B = g_WT       -> writes g_supportT (frag-major, tf32-rounded)
//   mode 1: B = g_supportT -> z = D + bias -> out_z ; student-t q -> out_q
// ---------------------------------------------------------------------------
__global__ void __launch_bounds__(THREADS)
gcn_mma_kernel(const float* __restrict__ A, int Kd, int mode,
               const float* __restrict__ bias, const float* __restrict__ mu,
               float* __restrict__ out_z, float* __restrict__ out_q)
{
    extern __shared__ float smem[];
    const uint32_t sbase = smem_u32(smem);
    const int tid  = threadIdx.x;
    const int row0 = blockIdx.x * MT;
    const int nchunks = (Kd + KC - 1) / KC;

    const float* __restrict__ BF = (mode == 0) ? g_WT : g_supportT;

    const int wid  = tid >> 5;
    const int lane = tid & 31;
    const int g    = lane >> 2;
    const int tig  = lane & 3;
    const bool full = (wid < 4);
    const int rb   = full ? wid * 16 : 64;   // quarter warps all work mtile 4
    const int ktq  = wid - 4;                // kt for quarter warps

    float acc[4][4];
#pragma unroll
    for (int nt = 0; nt < 4; nt++)
#pragma unroll
        for (int r = 0; r < 4; r++) acc[nt][r] = 0.0f;

    // ---- stage one K-chunk: A 640 float4 (row-major, padded) + B 256 float4 (contig)
    auto load_chunk = [&](int c) {
        const int s  = c & (NSTAGE - 1);
        const int k0 = c * KC;
        const uint32_t a_s = sbase + s * STAGE_BYTES;
        const uint32_t b_s = a_s + A_FLOATS * 4;
#pragma unroll
        for (int t = 0; t < 4; t++) {
            int idx = tid + t * THREADS;
            if (idx < 640) {
                int r   = idx >> 3;
                int c4  = idx & 7;
                int gk  = k0 + c4 * 4;
                int remk = Kd - gk;
                int bytes = remk >= 4 ? 16 : (remk > 0 ? remk * 4 : 0);
                const float* src = bytes ? (A + (size_t)(row0 + r) * Kd + gk) : A;
                cp_async16(a_s + (uint32_t)(r * A_STRIDE + c4 * 4) * 4, src, bytes);
            } else if (idx < 640 + 256) {
                int bi = idx - 640;
                cp_async16(b_s + (uint32_t)bi * 16, BF + (size_t)c * B_FLOATS + bi * 4, 16);
            }
        }
        asm volatile("cp.async.commit_group;" ::: "memory");
    };

    for (int c = 0; c < NSTAGE - 1; c++) load_chunk(c);

    // ---- mainloop ----
    for (int c = 0; c < nchunks; c++) {
        asm volatile("cp.async.wait_group %0;" :: "n"(NSTAGE - 2));
        __syncthreads();
        if (c + NSTAGE - 1 < nchunks) load_chunk(c + NSTAGE - 1);
        else asm volatile("cp.async.commit_group;" ::: "memory");

        const float* As = smem + (size_t)(c & (NSTAGE - 1)) * STAGE_FLOATS;
        const float4* B4 = reinterpret_cast<const float4*>(As + A_FLOATS);

        if (full) {
#pragma unroll
            for (int kt = 0; kt < 4; kt++)
                do_kt(As, B4, kt, rb, g, tig, acc);
        } else {
            do_kt(As, B4, ktq, rb, g, tig, acc);   // partial: this kt only
        }
    }
    __syncthreads();

    // ---- epilogue ----
    float* pbuf = smem + A_FLOATS;   // 4 x 512 floats partial buffer (mtile 4)
    if (mode == 0) {
        if (full) {
#pragma unroll
            for (int nt = 0; nt < 4; nt++)
#pragma unroll
                for (int r = 0; r < 4; r++) {
                    int m = row0 + rb + g + ((r & 2) ? 8 : 0);
                    int n = nt * 8 + tig * 2 + (r & 1);
                    store_frag(g_supportT, acc[nt][r], m, n);
                }
        } else {
#pragma unroll
            for (int nt = 0; nt < 4; nt++)
#pragma unroll
                for (int r = 0; r < 4; r++) {
                    int ml = g + ((r & 2) ? 8 : 0);
                    int n  = nt * 8 + tig * 2 + (r & 1);
                    pbuf[ktq * 512 + ml * 32 + n] = acc[nt][r];
                }
        }
        __syncthreads();
        // merge 512 entries with 256 threads (2 each) -- this was the R8 bug
#pragma unroll
        for (int t = tid; t < 512; t += THREADS) {
            float s = pbuf[t] + pbuf[512 + t] + pbuf[1024 + t] + pbuf[1536 + t];
            store_frag(g_supportT, s, row0 + 64 + (t >> 5), t & 31);
        }
    } else {
        float* zs = smem;   // [MT][A_STRIDE] staging (stage-0 A region)
        if (full) {
#pragma unroll
            for (int nt = 0; nt < 4; nt++)
#pragma unroll
                for (int r = 0; r < 4; r++) {
                    int rr = rb + g + ((r & 2) ? 8 : 0);
                    int n  = nt * 8 + tig * 2 + (r & 1);
                    zs[rr * A_STRIDE + n] = acc[nt][r] + __ldg(bias + n);
                }
        } else {
#pragma unroll
            for (int nt = 0; nt < 4; nt++)
#pragma unroll
                for (int r = 0; r < 4; r++) {
                    int ml = g + ((r & 2) ? 8 : 0);
                    int n  = nt * 8 + tig * 2 + (r & 1);
                    pbuf[ktq * 512 + ml * 32 + n] = acc[nt][r];
                }
        }
        __syncthreads();
        // merge 512 entries with 256 threads (2 each) -- this was the R8 bug
#pragma unroll
        for (int t = tid; t < 512; t += THREADS) {
            int n = t & 31;
            float s = pbuf[t] + pbuf[512 + t] + pbuf[1024 + t] + pbuf[1536 + t];
            zs[(64 + (t >> 5)) * A_STRIDE + n] = s + __ldg(bias + n);
        }
        __syncthreads();
        if (tid < MT) {
            const int m = row0 + tid;
            float z[NHID];
#pragma unroll
            for (int k = 0; k < NHID; k += 4) {
                float4 v = *reinterpret_cast<const float4*>(zs + tid * A_STRIDE + k);
                z[k] = v.x; z[k + 1] = v.y; z[k + 2] = v.z; z[k + 3] = v.w;
                *reinterpret_cast<float4*>(out_z + (size_t)m * NHID + k) = v;
            }
            float q[KCLUST];
            float qsum = 0.0f;
#pragma unroll
            for (int j = 0; j < KCLUST; j++) {
                float d2 = 0.0f;
#pragma unroll
                for (int k = 0; k < NHID; k++) {
                    float d = z[k] - __ldg(mu + j * NHID + k);
                    d2 = fmaf(d, d, d2);
                }
                float t  = 1.0f / (1.0f + d2 * (1.0f / ALPHAF) + 1e-8f);
                float qj = __powf(t, ALPHAF + 1.0f) * 0.5f;
                q[j] = qj;
                qsum += qj;
            }
            float inv = 1.0f / qsum;
#pragma unroll
            for (int j = 0; j < KCLUST; j++)
                out_q[(size_t)m * KCLUST + j] = q[j] * inv;
        }
    }
}

// ---------------------------------------------------------------------------
// Launch
// ---------------------------------------------------------------------------
extern "C" void kernel_launch(void* const* d_in, const int* in_sizes, int n_in,
                              void* d_out, int out_size)
{
    const float* x   = (const float*)d_in[0];   // [10000, 3000]
    const float* adj = (const float*)d_in[1];   // [10000, 10000]
    const float* W   = (const float*)d_in[2];   // [3000, 32]
    const float* b   = (const float*)d_in[3];   // [32]
    const float* mu  = (const float*)d_in[4];   // [10, 32]

    float* out   = (float*)d_out;
    float* out_z = out;                          // [10000, 32]
    float* out_q = out + (size_t)NROWS * NHID;   // [10000, 10]

    cudaFuncSetAttribute(gcn_mma_kernel,
                         cudaFuncAttributeMaxDynamicSharedMemorySize, SMEM_TOTAL);

    const int grid = NROWS / MT;   // 125, exact

    int ntr = CH1 * B_FLOATS + B_FLOATS;
    transposeW_kernel<<<(ntr + 255) / 256, 256>>>(W);
    gcn_mma_kernel<<<grid, THREADS, SMEM_TOTAL>>>(
        x, NFEAT, 0, nullptr, nullptr, nullptr, nullptr);
    gcn_mma_kernel<<<grid, THREADS, SMEM_TOTAL>>>(
        adj, NROWS, 1, b, mu, out_z, out_q);
}